// round 1
// baseline (speedup 1.0000x reference)
#include <cuda_runtime.h>
#include <cstdint>
#include <cstddef>

#define T_STEPS    64
#define INPUT_BITS 1024
#define N_STATE    2048
#define N_OUT      256
#define NBITS      16
#define HASH       65536

#define REC_BLOCKS  16
#define REC_THREADS 128   // 16 * 128 = 2048 -> one thread per state neuron

// -------- device scratch (static allocation only; no cudaMalloc allowed) ----
__device__ int      g_wbase[T_STEPS * N_STATE];     // window part of each address
__device__ unsigned g_state[2][N_STATE / 32];       // double-buffered packed state bits
__device__ unsigned g_barrier;                      // monotonic barrier counter

// -------- memory-model helpers (gpu-scope, morally strong) ------------------
__device__ __forceinline__ unsigned ld_relaxed_u32(const unsigned* p) {
    unsigned v;
    asm volatile("ld.relaxed.gpu.u32 %0, [%1];" : "=r"(v) : "l"(p) : "memory");
    return v;
}
__device__ __forceinline__ void st_relaxed_u32(unsigned* p, unsigned v) {
    asm volatile("st.relaxed.gpu.u32 [%0], %1;" :: "l"(p), "r"(v) : "memory");
}
__device__ __forceinline__ unsigned ld_acquire_u32(const unsigned* p) {
    unsigned v;
    asm volatile("ld.acquire.gpu.u32 %0, [%1];" : "=r"(v) : "l"(p) : "memory");
    return v;
}
__device__ __forceinline__ void red_release_add(unsigned* p, unsigned v) {
    asm volatile("red.release.gpu.add.u32 [%0], %1;" :: "l"(p), "r"(v) : "memory");
}

// ---------------------------------------------------------------------------
__global__ void init_kernel() {
    g_barrier = 0u;
}

// Precompute wbase[t][n] = sum over connections j with conn<1024 of window_bit << j.
// Fully parallel: grid (8, 64) x 256 threads, one thread per (t, n).
__global__ __launch_bounds__(256) void precompute_kernel(
    const int* __restrict__ input_bits,
    const int* __restrict__ conn_state)
{
    const int t = blockIdx.y;
    __shared__ unsigned win[INPUT_BITS / 32];   // 32 packed words

    const int lane = threadIdx.x & 31;
    const int warp = threadIdx.x >> 5;          // 8 warps -> 4 words each
#pragma unroll
    for (int k = 0; k < 4; k++) {
        const int w = warp * 4 + k;
        const int b = input_bits[t * INPUT_BITS + w * 32 + lane];
        const unsigned m = __ballot_sync(0xffffffffu, b != 0);
        if (lane == 0) win[w] = m;
    }
    __syncthreads();

    const int n = blockIdx.x * blockDim.x + threadIdx.x;   // 0..2047
    const int4* c4 = reinterpret_cast<const int4*>(conn_state) + n * 4;
    int c[16];
    {
        int4 a0 = c4[0], a1 = c4[1], a2 = c4[2], a3 = c4[3];
        c[0]=a0.x;  c[1]=a0.y;  c[2]=a0.z;  c[3]=a0.w;
        c[4]=a1.x;  c[5]=a1.y;  c[6]=a1.z;  c[7]=a1.w;
        c[8]=a2.x;  c[9]=a2.y;  c[10]=a2.z; c[11]=a2.w;
        c[12]=a3.x; c[13]=a3.y; c[14]=a3.z; c[15]=a3.w;
    }
    int acc = 0;
#pragma unroll
    for (int j = 0; j < 16; j++) {
        const int ci = c[j];
        if (ci < INPUT_BITS)
            acc += (int)((win[ci >> 5] >> (ci & 31)) & 1u) << j;
    }
    g_wbase[t * N_STATE + n] = acc;
}

// Persistent recurrence: 16 co-resident blocks, hand-rolled global barrier.
// Step t: read state buf[t&1] (skip t=0, state starts all-zero), gather state
// bits, addr = wbase + state part, 1 table lookup, ballot-pack new bits into
// buf[(t+1)&1]. Output layer folded in after the last barrier.
__global__ __launch_bounds__(REC_THREADS) void recurrent_kernel(
    const int*   __restrict__ conn_state,
    const float* __restrict__ state_table,
    const int*   __restrict__ conn_out,
    const float* __restrict__ output_table,
    float*       __restrict__ out)
{
    __shared__ unsigned sstate[N_STATE / 32];   // 64 words

    const int tid  = threadIdx.x;
    const int lane = tid & 31;
    const int warp = tid >> 5;                  // 0..3
    const int n    = blockIdx.x * REC_THREADS + tid;

    // Preload this neuron's connections; rebase so >=0 means state index.
    int c[16];
    {
        const int4* c4 = reinterpret_cast<const int4*>(conn_state) + n * 4;
        int4 a0 = c4[0], a1 = c4[1], a2 = c4[2], a3 = c4[3];
        c[0]=a0.x-INPUT_BITS;  c[1]=a0.y-INPUT_BITS;  c[2]=a0.z-INPUT_BITS;  c[3]=a0.w-INPUT_BITS;
        c[4]=a1.x-INPUT_BITS;  c[5]=a1.y-INPUT_BITS;  c[6]=a1.z-INPUT_BITS;  c[7]=a1.w-INPUT_BITS;
        c[8]=a2.x-INPUT_BITS;  c[9]=a2.y-INPUT_BITS;  c[10]=a2.z-INPUT_BITS; c[11]=a2.w-INPUT_BITS;
        c[12]=a3.x-INPUT_BITS; c[13]=a3.y-INPUT_BITS; c[14]=a3.z-INPUT_BITS; c[15]=a3.w-INPUT_BITS;
    }
    const float* trow = state_table + (size_t)n * HASH;

    unsigned target = 0;
    for (int t = 0; t < T_STEPS; t++) {
        int acc = g_wbase[t * N_STATE + n];     // independent of state; overlaps below

        if (t > 0) {
            if (tid < N_STATE / 32)
                sstate[tid] = ld_relaxed_u32(&g_state[t & 1][tid]);
            __syncthreads();
#pragma unroll
            for (int j = 0; j < 16; j++) {
                const int ci = c[j];
                if (ci >= 0)
                    acc += (int)((sstate[ci >> 5] >> (ci & 31)) & 1u) << j;
            }
        }

        const float v = __ldg(trow + acc);
        const unsigned bal = __ballot_sync(0xffffffffu, v > 0.5f);
        if (lane == 0)
            st_relaxed_u32(&g_state[(t + 1) & 1][blockIdx.x * 4 + warp], bal);

        __syncthreads();                         // block's writes done before release
        target += REC_BLOCKS;
        if (tid == 0) {
            red_release_add(&g_barrier, 1u);
            while (ld_acquire_u32(&g_barrier) < target) { }
        }
        __syncthreads();                         // acquire visible to whole block
    }

    // ---- output layer on final state (g_state[T&1] == g_state[0]) ----------
    if (blockIdx.x < 2) {
        if (tid < N_STATE / 32)
            sstate[tid] = ld_relaxed_u32(&g_state[0][tid]);
        __syncthreads();

        const int o = blockIdx.x * REC_THREADS + tid;     // 0..255
        const int4* c4 = reinterpret_cast<const int4*>(conn_out) + o * 4;
        int4 a0 = c4[0], a1 = c4[1], a2 = c4[2], a3 = c4[3];
        int co[16];
        co[0]=a0.x;  co[1]=a0.y;  co[2]=a0.z;  co[3]=a0.w;
        co[4]=a1.x;  co[5]=a1.y;  co[6]=a1.z;  co[7]=a1.w;
        co[8]=a2.x;  co[9]=a2.y;  co[10]=a2.z; co[11]=a2.w;
        co[12]=a3.x; co[13]=a3.y; co[14]=a3.z; co[15]=a3.w;

        int addr = 0;
#pragma unroll
        for (int j = 0; j < 16; j++) {
            const int ci = co[j];
            addr += (int)((sstate[ci >> 5] >> (ci & 31)) & 1u) << j;
        }
        out[o] = __ldg(output_table + (size_t)o * HASH + addr);
    }
}

// ---------------------------------------------------------------------------
extern "C" void kernel_launch(void* const* d_in, const int* in_sizes, int n_in,
                              void* d_out, int out_size)
{
    const int*   input_bits   = (const int*)  d_in[0];  // [65536]
    const int*   conn_state   = (const int*)  d_in[1];  // [2048*16]
    const int*   conn_out     = (const int*)  d_in[2];  // [256*16]
    const float* state_table  = (const float*)d_in[3];  // [2048*65536]
    const float* output_table = (const float*)d_in[4];  // [256*65536]
    float*       out          = (float*)d_out;          // [256]

    init_kernel<<<1, 1>>>();
    precompute_kernel<<<dim3(8, 64), 256>>>(input_bits, conn_state);
    recurrent_kernel<<<REC_BLOCKS, REC_THREADS>>>(conn_state, state_table,
                                                  conn_out, output_table, out);
}

// round 2
// speedup vs baseline: 1.4751x; 1.4751x over previous
#include <cuda_runtime.h>
#include <cstdint>
#include <cstddef>

#define T_STEPS    64
#define INPUT_BITS 1024
#define N_STATE    2048
#define N_OUT      256
#define HASH       65536

#define CLUSTER_CTAS 8
#define CTA_THREADS  256                      // 8 * 256 = 2048 -> 1 thread / state neuron
#define WORDS_PER_CTA (CTA_THREADS / 32)      // 8 ballot words per CTA
#define STATE_WORDS   (N_STATE / 32)          // 64 packed state words

// -------- device scratch (static allocation only) ---------------------------
__device__ int g_wbase[T_STEPS * N_STATE];    // window part of each address

// -------- helpers ------------------------------------------------------------
__device__ __forceinline__ uint32_t smem_u32(const void* p) {
    uint32_t a;
    asm("{ .reg .u64 t; cvta.to.shared.u64 t, %1; cvt.u32.u64 %0, t; }"
        : "=r"(a) : "l"(p));
    return a;
}
__device__ __forceinline__ uint32_t cluster_rank() {
    uint32_t r;
    asm("mov.u32 %0, %%cluster_ctarank;" : "=r"(r));
    return r;
}
__device__ __forceinline__ unsigned dsmem_ld_u32(uint32_t laddr, uint32_t rank) {
    uint32_t raddr; unsigned v;
    asm("mapa.shared::cluster.u32 %0, %1, %2;" : "=r"(raddr) : "r"(laddr), "r"(rank));
    asm volatile("ld.shared::cluster.u32 %0, [%1];" : "=r"(v) : "r"(raddr));
    return v;
}
#define CLUSTER_SYNC() do {                                              \
    asm volatile("barrier.cluster.arrive.aligned;" ::: "memory");        \
    asm volatile("barrier.cluster.wait.aligned;"   ::: "memory");        \
} while (0)

// ---------------------------------------------------------------------------
// Precompute wbase[t][n]: window-bit contribution to each state-neuron address.
// Fully parallel: grid (8, 64) x 256 threads, one thread per (t, n).
__global__ __launch_bounds__(256) void precompute_kernel(
    const int* __restrict__ input_bits,
    const int* __restrict__ conn_state)
{
    const int t = blockIdx.y;
    __shared__ unsigned win[INPUT_BITS / 32];   // 32 packed words

    const int lane = threadIdx.x & 31;
    const int warp = threadIdx.x >> 5;          // 8 warps -> 4 words each
#pragma unroll
    for (int k = 0; k < 4; k++) {
        const int w = warp * 4 + k;
        const int b = input_bits[t * INPUT_BITS + w * 32 + lane];
        const unsigned m = __ballot_sync(0xffffffffu, b != 0);
        if (lane == 0) win[w] = m;
    }
    __syncthreads();

    const int n = blockIdx.x * blockDim.x + threadIdx.x;   // 0..2047
    const int4* c4 = reinterpret_cast<const int4*>(conn_state) + n * 4;
    int c[16];
    {
        int4 a0 = c4[0], a1 = c4[1], a2 = c4[2], a3 = c4[3];
        c[0]=a0.x;  c[1]=a0.y;  c[2]=a0.z;  c[3]=a0.w;
        c[4]=a1.x;  c[5]=a1.y;  c[6]=a1.z;  c[7]=a1.w;
        c[8]=a2.x;  c[9]=a2.y;  c[10]=a2.z; c[11]=a2.w;
        c[12]=a3.x; c[13]=a3.y; c[14]=a3.z; c[15]=a3.w;
    }
    int acc = 0;
#pragma unroll
    for (int j = 0; j < 16; j++) {
        const int ci = c[j];
        if (ci < INPUT_BITS)
            acc += (int)((win[ci >> 5] >> (ci & 31)) & 1u) << j;
    }
    g_wbase[t * N_STATE + n] = acc;
}

// ---------------------------------------------------------------------------
// Recurrence as an 8-CTA cluster (2048 threads = 2048 state neurons).
// Per step: assemble full state from peers via DSMEM, gather 16 state bits,
// one L2-resident table lookup, ballot-pack into local smem, cluster barrier.
__global__ __launch_bounds__(CTA_THREADS)
__cluster_dims__(CLUSTER_CTAS, 1, 1)
void recurrent_kernel(
    const int*   __restrict__ conn_state,
    const float* __restrict__ state_table,
    const int*   __restrict__ conn_out,
    const float* __restrict__ output_table,
    float*       __restrict__ out)
{
    __shared__ unsigned mystate[2][WORDS_PER_CTA];  // this CTA's ballot words (dbl-buffered)
    __shared__ unsigned sstate[STATE_WORDS];        // assembled full state

    const int tid  = threadIdx.x;
    const int lane = tid & 31;
    const int warp = tid >> 5;
    const uint32_t rank = cluster_rank();
    const int n = (int)rank * CTA_THREADS + tid;    // my state neuron

    // Preload connections; rebase so >=0 means a state-bit index.
    int c[16];
    {
        const int4* c4 = reinterpret_cast<const int4*>(conn_state) + n * 4;
        int4 a0 = c4[0], a1 = c4[1], a2 = c4[2], a3 = c4[3];
        c[0]=a0.x-INPUT_BITS;  c[1]=a0.y-INPUT_BITS;  c[2]=a0.z-INPUT_BITS;  c[3]=a0.w-INPUT_BITS;
        c[4]=a1.x-INPUT_BITS;  c[5]=a1.y-INPUT_BITS;  c[6]=a1.z-INPUT_BITS;  c[7]=a1.w-INPUT_BITS;
        c[8]=a2.x-INPUT_BITS;  c[9]=a2.y-INPUT_BITS;  c[10]=a2.z-INPUT_BITS; c[11]=a2.w-INPUT_BITS;
        c[12]=a3.x-INPUT_BITS; c[13]=a3.y-INPUT_BITS; c[14]=a3.z-INPUT_BITS; c[15]=a3.w-INPUT_BITS;
    }
    const float* trow = state_table + (size_t)n * HASH;
    const uint32_t mystate_base = smem_u32(&mystate[0][0]);

    // Prefetch wbase one step ahead so its L2 latency overlaps the step.
    int wnext = __ldg(&g_wbase[n]);   // t = 0

    for (int t = 0; t < T_STEPS; t++) {
        int acc = wnext;
        if (t + 1 < T_STEPS)
            wnext = __ldg(&g_wbase[(t + 1) * N_STATE + n]);

        if (t > 0) {
            // Assemble full 2048-bit state from all 8 CTAs via DSMEM.
            if (tid < STATE_WORDS) {
                const uint32_t owner = (uint32_t)tid >> 3;       // tid / WORDS_PER_CTA
                const uint32_t widx  = (uint32_t)tid & 7;
                const uint32_t laddr =
                    mystate_base + (((uint32_t)((t - 1) & 1) * WORDS_PER_CTA + widx) << 2);
                sstate[tid] = dsmem_ld_u32(laddr, owner);
            }
            __syncthreads();
#pragma unroll
            for (int j = 0; j < 16; j++) {
                const int ci = c[j];
                if (ci >= 0)
                    acc += (int)((sstate[ci >> 5] >> (ci & 31)) & 1u) << j;
            }
        }

        const float v = __ldg(trow + acc);
        const unsigned bal = __ballot_sync(0xffffffffu, v > 0.5f);
        if (lane == 0)
            mystate[t & 1][warp] = bal;

        // Release my ballot words / acquire peers' (arrive=release, wait=acquire).
        CLUSTER_SYNC();
    }

    // ---- output layer on final state (written into buffer (T-1)&1 = 1) -----
    if (rank == 0) {
        if (tid < STATE_WORDS) {
            const uint32_t owner = (uint32_t)tid >> 3;
            const uint32_t widx  = (uint32_t)tid & 7;
            const uint32_t laddr =
                mystate_base + (((uint32_t)((T_STEPS - 1) & 1) * WORDS_PER_CTA + widx) << 2);
            sstate[tid] = dsmem_ld_u32(laddr, owner);
        }
        __syncthreads();
    }
    CLUSTER_SYNC();   // keep peer CTAs (and their smem) alive until rank0 has read

    if (rank == 0) {
        const int o = tid;                                  // 0..255
        const int4* c4 = reinterpret_cast<const int4*>(conn_out) + o * 4;
        int4 a0 = c4[0], a1 = c4[1], a2 = c4[2], a3 = c4[3];
        int co[16];
        co[0]=a0.x;  co[1]=a0.y;  co[2]=a0.z;  co[3]=a0.w;
        co[4]=a1.x;  co[5]=a1.y;  co[6]=a1.z;  co[7]=a1.w;
        co[8]=a2.x;  co[9]=a2.y;  co[10]=a2.z; co[11]=a2.w;
        co[12]=a3.x; co[13]=a3.y; co[14]=a3.z; co[15]=a3.w;

        int addr = 0;
#pragma unroll
        for (int j = 0; j < 16; j++) {
            const int ci = co[j];
            addr += (int)((sstate[ci >> 5] >> (ci & 31)) & 1u) << j;
        }
        out[o] = __ldg(output_table + (size_t)o * HASH + addr);
    }
}

// ---------------------------------------------------------------------------
extern "C" void kernel_launch(void* const* d_in, const int* in_sizes, int n_in,
                              void* d_out, int out_size)
{
    const int*   input_bits   = (const int*)  d_in[0];  // [65536]
    const int*   conn_state   = (const int*)  d_in[1];  // [2048*16]
    const int*   conn_out     = (const int*)  d_in[2];  // [256*16]
    const float* state_table  = (const float*)d_in[3];  // [2048*65536]
    const float* output_table = (const float*)d_in[4];  // [256*65536]
    float*       out          = (float*)d_out;          // [256]

    precompute_kernel<<<dim3(8, 64), 256>>>(input_bits, conn_state);
    recurrent_kernel<<<CLUSTER_CTAS, CTA_THREADS>>>(conn_state, state_table,
                                                    conn_out, output_table, out);
}